// round 1
// baseline (speedup 1.0000x reference)
#include <cuda_runtime.h>
#include <math.h>

// Problem constants
#define BB   256    // batch
#define TT   128    // seq len
#define EE   100    // embed dim
#define HH   100    // hidden
#define CC   255    // paths per batch
#define G4   400    // 4*H gates
#define D2   200    // 2*H
#define MLPD 300
#define SCOL 900    // 3 * MLPD

// ---------------- scratch (device globals; no allocation allowed) -------------
__device__ float d_Wt_in[100 * 800];           // [k][col] col<400: fwd, else bwd
__device__ float d_bsum[800];                  // bih+bhh per direction
__device__ float d_gin[2 * TT * BB * G4];      // [dir][t][b][j] input gate part
__device__ float d_h2[BB * TT * D2];           // [b][t][2H] concat(hf,hb)
__device__ float d_WtS[200 * SCOL];            // [k][s*300+m] = W1[s*200+k][m]
__device__ float d_S[BB * TT * SCOL];          // per-(b,t) partial MLP products

// ---------------- setup: weight transposes + bias fold ------------------------
__global__ void setup_k(const float* __restrict__ Wih_f, const float* __restrict__ Wih_b,
                        const float* __restrict__ bih_f, const float* __restrict__ bhh_f,
                        const float* __restrict__ bih_b, const float* __restrict__ bhh_b,
                        const float* __restrict__ W1) {
    int stride = gridDim.x * blockDim.x;
    int i0 = blockIdx.x * blockDim.x + threadIdx.x;
    for (int idx = i0; idx < 100 * 800; idx += stride) {
        int k = idx / 800, col = idx % 800;
        d_Wt_in[idx] = (col < 400) ? Wih_f[col * 100 + k] : Wih_b[(col - 400) * 100 + k];
    }
    for (int idx = i0; idx < 800; idx += stride) {
        d_bsum[idx] = (idx < 400) ? (bih_f[idx] + bhh_f[idx])
                                  : (bih_b[idx - 400] + bhh_b[idx - 400]);
    }
    for (int idx = i0; idx < 200 * SCOL; idx += stride) {
        int k = idx / SCOL, col = idx % SCOL;
        int s = col / MLPD, m = col % MLPD;
        d_WtS[idx] = W1[(s * 200 + k) * MLPD + m];
    }
}

// ---------------- kernel A: embedding gather + input-gate GEMM ----------------
// rows r = t*B + b over (T*B, 100) @ (100, 800). R=64 rows/block, 160 col-threads.
__global__ __launch_bounds__(160) void input_gates_k(const int* __restrict__ x,
                                                     const float* __restrict__ emb) {
    __shared__ float xs[64 * 100];
    __shared__ int toks[64];
    const int r0 = blockIdx.x * 64;
    const int col = blockIdx.y * 160 + threadIdx.x;
    const int tid = threadIdx.x;

    if (tid < 64) {
        int r = r0 + tid;
        int t = r / BB, b = r % BB;
        toks[tid] = x[b * TT + t];
    }
    __syncthreads();
    for (int idx = tid; idx < 64 * 100; idx += 160) {
        int i = idx / 100, k = idx % 100;
        xs[idx] = emb[(long)toks[i] * EE + k];
    }
    __syncthreads();

    float acc[64];
    const float bias = d_bsum[col];
#pragma unroll
    for (int i = 0; i < 64; i++) acc[i] = bias;

    for (int k = 0; k < 100; k++) {
        float w = d_Wt_in[k * 800 + col];
#pragma unroll
        for (int i = 0; i < 64; i++) acc[i] = fmaf(xs[i * 100 + k], w, acc[i]);
    }

    const int dir = (col >= 400) ? 1 : 0;
    const int j = col - dir * 400;
#pragma unroll 4
    for (int i = 0; i < 64; i++) {
        int r = r0 + i;
        int t = r / BB, b = r % BB;
        d_gin[((dir * TT + t) * BB + b) * G4 + j] = acc[i];
    }
}

// ---------------- kernel B: persistent batch-sliced BiLSTM recurrence ---------
// 128 blocks: blockIdx/64 = dir, (blockIdx%64)*4 = batch base. Whh in smem.
__device__ __forceinline__ float sigf(float v) { return 1.0f / (1.0f + __expf(-v)); }

__global__ __launch_bounds__(416, 1) void lstm_k(const float* __restrict__ Whh_f,
                                                 const float* __restrict__ Whh_b) {
    extern __shared__ float sm[];
    float* Wsh = sm;              // 40000 floats (400x100)
    float* hsh = sm + 40000;      // 400  [b*100 + k]
    float* gsh = sm + 40400;      // 1600 [b*400 + j]

    const int tid = threadIdx.x;
    const int dir = blockIdx.x >> 6;
    const int b0 = (blockIdx.x & 63) * 4;
    const float* __restrict__ Whh = dir ? Whh_b : Whh_f;

    float4* Wsh4 = (float4*)Wsh;
    const float4* Wg4 = (const float4*)Whh;
    for (int idx = tid; idx < 10000; idx += 416) Wsh4[idx] = Wg4[idx];
    for (int idx = tid; idx < 400; idx += 416) hsh[idx] = 0.0f;
    __syncthreads();

    float c = 0.0f;
    const int bb = tid / 100;   // valid when tid<400
    const int hid = tid % 100;
    const float4* h4 = (const float4*)hsh;

    for (int step = 0; step < TT; ++step) {
        const int t = dir ? (TT - 1 - step) : step;
        if (tid < 400) {
            const int j = tid;
            const float* gp = &d_gin[((dir * TT + t) * BB + b0) * G4 + j];
            float a0 = gp[0], a1 = gp[G4], a2 = gp[2 * G4], a3 = gp[3 * G4];
            const float4* wr = Wsh4 + j * 25;
#pragma unroll
            for (int kk = 0; kk < 25; ++kk) {
                float4 w = wr[kk];
                float4 v0 = h4[kk];
                float4 v1 = h4[25 + kk];
                float4 v2 = h4[50 + kk];
                float4 v3 = h4[75 + kk];
                a0 = fmaf(w.x, v0.x, fmaf(w.y, v0.y, fmaf(w.z, v0.z, fmaf(w.w, v0.w, a0))));
                a1 = fmaf(w.x, v1.x, fmaf(w.y, v1.y, fmaf(w.z, v1.z, fmaf(w.w, v1.w, a1))));
                a2 = fmaf(w.x, v2.x, fmaf(w.y, v2.y, fmaf(w.z, v2.z, fmaf(w.w, v2.w, a2))));
                a3 = fmaf(w.x, v3.x, fmaf(w.y, v3.y, fmaf(w.z, v3.z, fmaf(w.w, v3.w, a3))));
            }
            gsh[0 * G4 + j] = a0;
            gsh[1 * G4 + j] = a1;
            gsh[2 * G4 + j] = a2;
            gsh[3 * G4 + j] = a3;
        }
        __syncthreads();
        if (tid < 400) {
            float gi = gsh[bb * G4 + hid];
            float gf = gsh[bb * G4 + hid + 100];
            float gg = gsh[bb * G4 + hid + 200];
            float go = gsh[bb * G4 + hid + 300];
            c = sigf(gf) * c + sigf(gi) * tanhf(gg);
            float h = sigf(go) * tanhf(c);
            hsh[bb * 100 + hid] = h;
            d_h2[((b0 + bb) * TT + t) * D2 + dir * HH + hid] = h;
        }
        __syncthreads();
    }
}

// ---------------- kernel C: S-GEMM (32768,200) @ (200,900) --------------------
// R=64 rows/block, 300 active col-threads, grid (512, 3).
__global__ __launch_bounds__(320) void sgemm_k() {
    extern __shared__ float xs[];   // 64*200 floats
    const int tid = threadIdx.x;
    const int r0 = blockIdx.x * 64;

    for (int idx = tid; idx < 64 * 200; idx += 320)
        xs[idx] = d_h2[r0 * D2 + idx];
    __syncthreads();

    if (tid >= 300) return;
    const int col = blockIdx.y * MLPD + tid;

    float acc[64];
#pragma unroll
    for (int i = 0; i < 64; i++) acc[i] = 0.0f;

    for (int k = 0; k < 200; k++) {
        float w = d_WtS[k * SCOL + col];
#pragma unroll
        for (int i = 0; i < 64; i++) acc[i] = fmaf(xs[i * 200 + k], w, acc[i]);
    }
#pragma unroll 4
    for (int i = 0; i < 64; i++) d_S[(long)(r0 + i) * SCOL + col] = acc[i];
}

// ---------------- kernel D: gather + tanh + (300->3) + softmax ----------------
__global__ __launch_bounds__(256) void combine_k(const int* __restrict__ paths,
                                                 const float* __restrict__ b1,
                                                 const float* __restrict__ W2,
                                                 const float* __restrict__ b2,
                                                 float* __restrict__ out) {
    const int warp = (blockIdx.x * blockDim.x + threadIdx.x) >> 5;
    const int lane = threadIdx.x & 31;
    if (warp >= BB * CC) return;
    const int b = warp / CC;

    const int* p = &paths[warp * 3];
    int p0 = __ldg(p), p1 = __ldg(p + 1), p2 = __ldg(p + 2);
    int i0 = min(max(p0, 0), TT - 1);
    int i1 = min(max(p1, 0), TT - 1);
    int i2 = min(max(p2, 0), TT - 1);

    const float* S0 = &d_S[(long)(b * TT + i0) * SCOL];
    const float* S1 = &d_S[(long)(b * TT + i1) * SCOL + 300];
    const float* S2 = &d_S[(long)(b * TT + i2) * SCOL + 600];

    float z0 = 0.f, z1 = 0.f, z2 = 0.f;
    for (int m = lane; m < MLPD; m += 32) {
        float hv = __ldg(&b1[m]);
        if (p0 >= 0) hv += S0[m];
        if (p1 >= 0) hv += S1[m];
        if (p2 >= 0) hv += S2[m];
        hv = tanhf(hv);
        z0 = fmaf(hv, __ldg(&W2[m * 3 + 0]), z0);
        z1 = fmaf(hv, __ldg(&W2[m * 3 + 1]), z1);
        z2 = fmaf(hv, __ldg(&W2[m * 3 + 2]), z2);
    }
#pragma unroll
    for (int off = 16; off; off >>= 1) {
        z0 += __shfl_xor_sync(0xFFFFFFFFu, z0, off);
        z1 += __shfl_xor_sync(0xFFFFFFFFu, z1, off);
        z2 += __shfl_xor_sync(0xFFFFFFFFu, z2, off);
    }
    if (lane == 0) {
        z0 += __ldg(&b2[0]); z1 += __ldg(&b2[1]); z2 += __ldg(&b2[2]);
        float mx = fmaxf(z0, fmaxf(z1, z2));
        float e0 = __expf(z0 - mx), e1 = __expf(z1 - mx), e2 = __expf(z2 - mx);
        float inv = 1.0f / (e0 + e1 + e2);
        out[warp * 3 + 0] = e0 * inv;
        out[warp * 3 + 1] = e1 * inv;
        out[warp * 3 + 2] = e2 * inv;
    }
}

// -------------------------------- launch --------------------------------------
extern "C" void kernel_launch(void* const* d_in, const int* in_sizes, int n_in,
                              void* d_out, int out_size) {
    const int*   x     = (const int*)  d_in[0];
    const int*   paths = (const int*)  d_in[1];
    const float* emb   = (const float*)d_in[2];
    const float* Wih_f = (const float*)d_in[3];
    const float* Whh_f = (const float*)d_in[4];
    const float* bih_f = (const float*)d_in[5];
    const float* bhh_f = (const float*)d_in[6];
    const float* Wih_b = (const float*)d_in[7];
    const float* Whh_b = (const float*)d_in[8];
    const float* bih_b = (const float*)d_in[9];
    const float* bhh_b = (const float*)d_in[10];
    const float* W1    = (const float*)d_in[11];
    const float* b1    = (const float*)d_in[12];
    const float* W2    = (const float*)d_in[13];
    const float* b2    = (const float*)d_in[14];
    float* out = (float*)d_out;

    // opt-in smem (idempotent, host-side; not a graph node)
    cudaFuncSetAttribute(lstm_k, cudaFuncAttributeMaxDynamicSharedMemorySize, 42000 * 4);
    cudaFuncSetAttribute(sgemm_k, cudaFuncAttributeMaxDynamicSharedMemorySize, 64 * 200 * 4);

    setup_k<<<64, 256>>>(Wih_f, Wih_b, bih_f, bhh_f, bih_b, bhh_b, W1);

    // A: (32768,100)@(100,800); grid rows 32768/64=512, cols 800/160=5
    {
        dim3 g(512, 5);
        input_gates_k<<<g, 160>>>(x, emb);
    }

    // B: persistent recurrence, 128 blocks (64/dir), 168KB dyn smem
    lstm_k<<<128, 416, 42000 * 4>>>(Whh_f, Whh_b);

    // C: (32768,200)@(200,900); grid (512, 3)
    {
        dim3 g(512, 3);
        sgemm_k<<<g, 320, 64 * 200 * 4>>>();
    }

    // D: 65280 rows, 1 warp each
    {
        int warps = BB * CC;
        int blocks = (warps * 32 + 255) / 256;
        combine_k<<<blocks, 256>>>(paths, b1, W2, b2, out);
    }
}

// round 2
// speedup vs baseline: 1.1442x; 1.1442x over previous
#include <cuda_runtime.h>
#include <math.h>

// Problem constants
#define BB   256    // batch
#define TT   128    // seq len
#define EE   100    // embed dim
#define HH   100    // hidden
#define CC   255    // paths per batch
#define G4   400    // 4*H gates
#define D2   200    // 2*H
#define MLPD 300
#define SCOL 900    // 3 * MLPD

typedef unsigned long long ULL;

__device__ __forceinline__ void ffma2(ULL& acc, ULL a, ULL b) {
    asm volatile("fma.rn.f32x2 %0, %1, %2, %0;" : "+l"(acc) : "l"(a), "l"(b));
}
__device__ __forceinline__ ULL pack2(float x, float y) {
    ULL r; asm("mov.b64 %0, {%1,%2};" : "=l"(r) : "f"(x), "f"(y)); return r;
}
__device__ __forceinline__ float2 unpack2(ULL v) {
    float2 r; asm("mov.b64 {%0,%1}, %2;" : "=f"(r.x), "=f"(r.y) : "l"(v)); return r;
}

// ---------------- scratch (device globals; no allocation allowed) -------------
__device__ float d_Wt_in[100 * 800];           // [k][col] col<400: fwd, else bwd
__device__ float d_bsum[800];                  // bih+bhh per direction
__device__ float d_gin[2 * TT * BB * G4];      // [dir][t][b][j] input gate part
__device__ float d_h2[BB * TT * D2];           // [b][t][2H] concat(hf,hb)
__device__ float d_WtS[200 * SCOL];            // [k][s*300+m] = W1[s*200+k][m]
__device__ float d_S[BB * TT * SCOL];          // per-(b,t) partial MLP products

// ---------------- setup: weight transposes + bias fold ------------------------
__global__ void setup_k(const float* __restrict__ Wih_f, const float* __restrict__ Wih_b,
                        const float* __restrict__ bih_f, const float* __restrict__ bhh_f,
                        const float* __restrict__ bih_b, const float* __restrict__ bhh_b,
                        const float* __restrict__ W1) {
    int stride = gridDim.x * blockDim.x;
    int i0 = blockIdx.x * blockDim.x + threadIdx.x;
    for (int idx = i0; idx < 100 * 800; idx += stride) {
        int k = idx / 800, col = idx % 800;
        d_Wt_in[idx] = (col < 400) ? Wih_f[col * 100 + k] : Wih_b[(col - 400) * 100 + k];
    }
    for (int idx = i0; idx < 800; idx += stride) {
        d_bsum[idx] = (idx < 400) ? (bih_f[idx] + bhh_f[idx])
                                  : (bih_b[idx - 400] + bhh_b[idx - 400]);
    }
    for (int idx = i0; idx < 200 * SCOL; idx += stride) {
        int k = idx / SCOL, col = idx % SCOL;
        int s = col / MLPD, m = col % MLPD;
        d_WtS[idx] = W1[(s * 200 + k) * MLPD + m];
    }
}

// ---------------- kernel A: embedding gather + input-gate GEMM ----------------
// Tiled GEMM (32768,100)@(100,800), BM=128 BN=100 BK=20, TM=8 TN=4, f32x2 FMA.
// Row r = t*BB + b.
__global__ __launch_bounds__(400) void input_gates_k(const int* __restrict__ x,
                                                     const float* __restrict__ emb) {
    __shared__ ULL   Asp[20][128];   // duplicated (a,a) pairs
    __shared__ float Bs[20][100];
    __shared__ int   toks[128];

    const int tid = threadIdx.x;
    const int tx = tid % 25, ty = tid / 25;
    const int r0 = blockIdx.x * 128;
    const int c0 = blockIdx.y * 100;

    if (tid < 128) {
        int r = r0 + tid;
        int t = r >> 8, b = r & 255;
        toks[tid] = x[b * TT + t];
    }

    ULL acc[8][2];
    {
        ULL b0 = *(const ULL*)&d_bsum[c0 + tx * 4];
        ULL b1 = *(const ULL*)&d_bsum[c0 + tx * 4 + 2];
#pragma unroll
        for (int i = 0; i < 8; i++) { acc[i][0] = b0; acc[i][1] = b1; }
    }
    __syncthreads();

    for (int kc = 0; kc < 100; kc += 20) {
        for (int idx = tid; idx < 128 * 20; idx += 400) {
            int row = idx / 20, kk = idx % 20;
            float v = emb[(long)toks[row] * EE + kc + kk];
            Asp[kk][row] = pack2(v, v);
        }
        for (int idx = tid; idx < 2000; idx += 400) {
            int kk = idx / 100, n = idx % 100;
            Bs[kk][n] = d_Wt_in[(kc + kk) * 800 + c0 + n];
        }
        __syncthreads();
#pragma unroll
        for (int kk = 0; kk < 20; kk++) {
            ULL b0 = *(const ULL*)&Bs[kk][tx * 4];
            ULL b1 = *(const ULL*)&Bs[kk][tx * 4 + 2];
#pragma unroll
            for (int i = 0; i < 8; i++) {
                ULL a = Asp[kk][ty * 8 + i];
                ffma2(acc[i][0], a, b0);
                ffma2(acc[i][1], a, b1);
            }
        }
        __syncthreads();
    }

    const int c = c0 + tx * 4;            // all 4 cols within same 100-block => same dir
    const int dir = (c >= 400) ? 1 : 0;
    const int jj = c - dir * 400;
#pragma unroll
    for (int i = 0; i < 8; i++) {
        int r = r0 + ty * 8 + i;
        int t = r >> 8, b = r & 255;
        float2 v0 = unpack2(acc[i][0]);
        float2 v1 = unpack2(acc[i][1]);
        float4 out = make_float4(v0.x, v0.y, v1.x, v1.y);
        *(float4*)&d_gin[((dir * TT + t) * BB + b) * G4 + jj] = out;
    }
}

// ---------------- kernel B: persistent batch-sliced BiLSTM recurrence ---------
// 128 blocks: blockIdx/64 = dir, (blockIdx%64)*4 = batch base. Whh in smem.
__device__ __forceinline__ float sigf(float v) { return 1.0f / (1.0f + __expf(-v)); }

__global__ __launch_bounds__(416, 1) void lstm_k(const float* __restrict__ Whh_f,
                                                 const float* __restrict__ Whh_b) {
    extern __shared__ float sm[];
    float* Wsh = sm;              // 40000 floats (400x100)
    float* hsh = sm + 40000;      // 400  [b*100 + k]
    float* gsh = sm + 40400;      // 1600 [b*400 + j]

    const int tid = threadIdx.x;
    const int dir = blockIdx.x >> 6;
    const int b0 = (blockIdx.x & 63) * 4;
    const float* __restrict__ Whh = dir ? Whh_b : Whh_f;

    float4* Wsh4 = (float4*)Wsh;
    const float4* Wg4 = (const float4*)Whh;
    for (int idx = tid; idx < 10000; idx += 416) Wsh4[idx] = Wg4[idx];
    for (int idx = tid; idx < 400; idx += 416) hsh[idx] = 0.0f;
    __syncthreads();

    float c = 0.0f;
    const int bb = tid / 100;   // valid when tid<400
    const int hid = tid % 100;
    const ulonglong2* Wsh2 = (const ulonglong2*)Wsh;   // [j*25 + kk]
    const ulonglong2* h2p  = (const ulonglong2*)hsh;   // [b*25 + kk]

    for (int step = 0; step < TT; ++step) {
        const int t = dir ? (TT - 1 - step) : step;
        if (tid < 400) {
            const int j = tid;
            const float* gp = &d_gin[((dir * TT + t) * BB + b0) * G4 + j];
            float g0 = gp[0], g1 = gp[G4], g2 = gp[2 * G4], g3 = gp[3 * G4];
            ULL s0 = 0, s1 = 0, s2 = 0, s3 = 0;
            const ulonglong2* wr = Wsh2 + j * 25;
#pragma unroll
            for (int kk = 0; kk < 25; ++kk) {
                ulonglong2 w = wr[kk];
                ulonglong2 v0 = h2p[kk];
                ulonglong2 v1 = h2p[25 + kk];
                ulonglong2 v2 = h2p[50 + kk];
                ulonglong2 v3 = h2p[75 + kk];
                ffma2(s0, w.x, v0.x); ffma2(s0, w.y, v0.y);
                ffma2(s1, w.x, v1.x); ffma2(s1, w.y, v1.y);
                ffma2(s2, w.x, v2.x); ffma2(s2, w.y, v2.y);
                ffma2(s3, w.x, v3.x); ffma2(s3, w.y, v3.y);
            }
            float2 f0 = unpack2(s0), f1 = unpack2(s1), f2 = unpack2(s2), f3 = unpack2(s3);
            gsh[0 * G4 + j] = g0 + f0.x + f0.y;
            gsh[1 * G4 + j] = g1 + f1.x + f1.y;
            gsh[2 * G4 + j] = g2 + f2.x + f2.y;
            gsh[3 * G4 + j] = g3 + f3.x + f3.y;
        }
        __syncthreads();
        if (tid < 400) {
            float gi = gsh[bb * G4 + hid];
            float gf = gsh[bb * G4 + hid + 100];
            float gg = gsh[bb * G4 + hid + 200];
            float go = gsh[bb * G4 + hid + 300];
            c = sigf(gf) * c + sigf(gi) * tanhf(gg);
            float h = sigf(go) * tanhf(c);
            hsh[bb * 100 + hid] = h;
            d_h2[((b0 + bb) * TT + t) * D2 + dir * HH + hid] = h;
        }
        __syncthreads();
    }
}

// ---------------- kernel C: S-GEMM (32768,200) @ (200,900) --------------------
// Tiled, BM=128 BN=100 BK=20, TM=8 TN=4, f32x2 FMA. grid (256, 9).
__global__ __launch_bounds__(400) void sgemm_k() {
    __shared__ ULL   Asp[20][128];
    __shared__ float Bs[20][100];

    const int tid = threadIdx.x;
    const int tx = tid % 25, ty = tid / 25;
    const int r0 = blockIdx.x * 128;
    const int c0 = blockIdx.y * 100;

    ULL acc[8][2];
#pragma unroll
    for (int i = 0; i < 8; i++) { acc[i][0] = 0ull; acc[i][1] = 0ull; }

    for (int kc = 0; kc < 200; kc += 20) {
        for (int idx = tid; idx < 128 * 20; idx += 400) {
            int row = idx / 20, kk = idx % 20;
            float v = d_h2[(r0 + row) * D2 + kc + kk];
            Asp[kk][row] = pack2(v, v);
        }
        for (int idx = tid; idx < 2000; idx += 400) {
            int kk = idx / 100, n = idx % 100;
            Bs[kk][n] = d_WtS[(kc + kk) * SCOL + c0 + n];
        }
        __syncthreads();
#pragma unroll
        for (int kk = 0; kk < 20; kk++) {
            ULL b0 = *(const ULL*)&Bs[kk][tx * 4];
            ULL b1 = *(const ULL*)&Bs[kk][tx * 4 + 2];
#pragma unroll
            for (int i = 0; i < 8; i++) {
                ULL a = Asp[kk][ty * 8 + i];
                ffma2(acc[i][0], a, b0);
                ffma2(acc[i][1], a, b1);
            }
        }
        __syncthreads();
    }

#pragma unroll
    for (int i = 0; i < 8; i++) {
        int r = r0 + ty * 8 + i;
        float2 v0 = unpack2(acc[i][0]);
        float2 v1 = unpack2(acc[i][1]);
        float4 out = make_float4(v0.x, v0.y, v1.x, v1.y);
        *(float4*)&d_S[(long)r * SCOL + c0 + tx * 4] = out;
    }
}

// ---------------- kernel D: gather + tanh + (300->3) + softmax ----------------
__global__ __launch_bounds__(256) void combine_k(const int* __restrict__ paths,
                                                 const float* __restrict__ b1,
                                                 const float* __restrict__ W2,
                                                 const float* __restrict__ b2,
                                                 float* __restrict__ out) {
    const int warp = (blockIdx.x * blockDim.x + threadIdx.x) >> 5;
    const int lane = threadIdx.x & 31;
    if (warp >= BB * CC) return;
    const int b = warp / CC;

    const int* p = &paths[warp * 3];
    int p0 = __ldg(p), p1 = __ldg(p + 1), p2 = __ldg(p + 2);
    int i0 = min(max(p0, 0), TT - 1);
    int i1 = min(max(p1, 0), TT - 1);
    int i2 = min(max(p2, 0), TT - 1);

    const float* S0 = &d_S[(long)(b * TT + i0) * SCOL];
    const float* S1 = &d_S[(long)(b * TT + i1) * SCOL + 300];
    const float* S2 = &d_S[(long)(b * TT + i2) * SCOL + 600];

    float z0 = 0.f, z1 = 0.f, z2 = 0.f;
    for (int m = lane; m < MLPD; m += 32) {
        float hv = __ldg(&b1[m]);
        if (p0 >= 0) hv += S0[m];
        if (p1 >= 0) hv += S1[m];
        if (p2 >= 0) hv += S2[m];
        hv = tanhf(hv);
        z0 = fmaf(hv, __ldg(&W2[m * 3 + 0]), z0);
        z1 = fmaf(hv, __ldg(&W2[m * 3 + 1]), z1);
        z2 = fmaf(hv, __ldg(&W2[m * 3 + 2]), z2);
    }
#pragma unroll
    for (int off = 16; off; off >>= 1) {
        z0 += __shfl_xor_sync(0xFFFFFFFFu, z0, off);
        z1 += __shfl_xor_sync(0xFFFFFFFFu, z1, off);
        z2 += __shfl_xor_sync(0xFFFFFFFFu, z2, off);
    }
    if (lane == 0) {
        z0 += __ldg(&b2[0]); z1 += __ldg(&b2[1]); z2 += __ldg(&b2[2]);
        float mx = fmaxf(z0, fmaxf(z1, z2));
        float e0 = __expf(z0 - mx), e1 = __expf(z1 - mx), e2 = __expf(z2 - mx);
        float inv = 1.0f / (e0 + e1 + e2);
        out[warp * 3 + 0] = e0 * inv;
        out[warp * 3 + 1] = e1 * inv;
        out[warp * 3 + 2] = e2 * inv;
    }
}

// -------------------------------- launch --------------------------------------
extern "C" void kernel_launch(void* const* d_in, const int* in_sizes, int n_in,
                              void* d_out, int out_size) {
    const int*   x     = (const int*)  d_in[0];
    const int*   paths = (const int*)  d_in[1];
    const float* emb   = (const float*)d_in[2];
    const float* Wih_f = (const float*)d_in[3];
    const float* Whh_f = (const float*)d_in[4];
    const float* bih_f = (const float*)d_in[5];
    const float* bhh_f = (const float*)d_in[6];
    const float* Wih_b = (const float*)d_in[7];
    const float* Whh_b = (const float*)d_in[8];
    const float* bih_b = (const float*)d_in[9];
    const float* bhh_b = (const float*)d_in[10];
    const float* W1    = (const float*)d_in[11];
    const float* b1    = (const float*)d_in[12];
    const float* W2    = (const float*)d_in[13];
    const float* b2    = (const float*)d_in[14];
    float* out = (float*)d_out;

    cudaFuncSetAttribute(lstm_k, cudaFuncAttributeMaxDynamicSharedMemorySize, 42000 * 4);

    setup_k<<<64, 256>>>(Wih_f, Wih_b, bih_f, bhh_f, bih_b, bhh_b, W1);

    // A: tiled (32768,100)@(100,800): grid (256 rows, 8 col-tiles)
    {
        dim3 g(256, 8);
        input_gates_k<<<g, 400>>>(x, emb);
    }

    // B: persistent recurrence, 128 blocks (64/dir), 168KB dyn smem
    lstm_k<<<128, 416, 42000 * 4>>>(Whh_f, Whh_b);

    // C: tiled (32768,200)@(200,900): grid (256, 9)
    {
        dim3 g(256, 9);
        sgemm_k<<<g, 400>>>();
    }

    // D: 65280 rows, 1 warp each
    {
        int warps = BB * CC;
        int blocks = (warps * 32 + 255) / 256;
        combine_k<<<blocks, 256>>>(paths, b1, W2, b2, out);
    }
}

// round 3
// speedup vs baseline: 1.7282x; 1.5105x over previous
#include <cuda_runtime.h>
#include <math.h>

#define BB   256
#define TT   128
#define EE   100
#define HH   100
#define CC   255
#define MLPD 300
#define MROWS 32768        // B*T
#define NPAD 1024

typedef unsigned long long ULL;

__device__ __forceinline__ void ffma2(ULL& acc, ULL a, ULL b) {
    asm volatile("fma.rn.f32x2 %0, %1, %2, %0;" : "+l"(acc) : "l"(a), "l"(b));
}
__device__ __forceinline__ ULL pack2(float x, float y) {
    ULL r; asm("mov.b64 %0, {%1,%2};" : "=l"(r) : "f"(x), "f"(y)); return r;
}
__device__ __forceinline__ float2 unpack2(ULL v) {
    float2 r; asm("mov.b64 {%0,%1}, %2;" : "=f"(r.x), "=f"(r.y) : "l"(v)); return r;
}
__device__ __forceinline__ float tanhf_fast(float x) {
    float r; asm("tanh.approx.f32 %0, %1;" : "=f"(r) : "f"(x)); return r;
}
__device__ __forceinline__ float sigf(float x) { return 0.5f * tanhf_fast(0.5f * x) + 0.5f; }

// ---------------- device-global scratch ----------------------------------------
__device__ ULL   d_xeT[100 * MROWS];        // A for gates GEMM: dup pairs, [k][r], r=t*256+b
__device__ float d_WtIn[100 * NPAD];        // [k][col] col<800 valid (400 fwd | 400 bwd)
__device__ float d_bsum[NPAD];              // fused biases, padded
__device__ float d_gin[MROWS * NPAD];       // [r=t*256+b][col] col = dir*400 + gate*100 + hid
__device__ ULL   d_h2T[200 * MROWS];        // A for S GEMM: dup pairs, [k=dir*100+hid][r=b*128+t]
__device__ float d_WtS[200 * NPAD];         // [k][s*300+m], cols>=900 zero
__device__ float d_S[MROWS * NPAD];         // [r=b*128+t][col]

// ---------------- prep: weight transposes, pads, bias fold ----------------------
__global__ void prep_k(const float* __restrict__ Wih_f, const float* __restrict__ Wih_b,
                       const float* __restrict__ bih_f, const float* __restrict__ bhh_f,
                       const float* __restrict__ bih_b, const float* __restrict__ bhh_b,
                       const float* __restrict__ W1) {
    int stride = gridDim.x * blockDim.x;
    int i0 = blockIdx.x * blockDim.x + threadIdx.x;
    for (int idx = i0; idx < 100 * NPAD; idx += stride) {
        int k = idx / NPAD, col = idx % NPAD;
        float v = 0.0f;
        if (col < 400)      v = Wih_f[col * 100 + k];
        else if (col < 800) v = Wih_b[(col - 400) * 100 + k];
        d_WtIn[idx] = v;
    }
    for (int idx = i0; idx < NPAD; idx += stride) {
        float v = 0.0f;
        if (idx < 400)      v = bih_f[idx] + bhh_f[idx];
        else if (idx < 800) v = bih_b[idx - 400] + bhh_b[idx - 400];
        d_bsum[idx] = v;
    }
    for (int idx = i0; idx < 200 * NPAD; idx += stride) {
        int k = idx / NPAD, col = idx % NPAD;
        float v = 0.0f;
        if (col < 900) {
            int s = col / MLPD, m = col % MLPD;
            v = W1[(s * 200 + k) * MLPD + m];
        }
        d_WtS[idx] = v;
    }
}

// ---------------- embed gather + transpose + duplicate --------------------------
__global__ __launch_bounds__(512) void xet_k(const int* __restrict__ x,
                                             const float* __restrict__ emb) {
    __shared__ float sh[128][101];
    __shared__ int toks[128];
    const int tid = threadIdx.x;
    const int r0 = blockIdx.x * 128;
    if (tid < 128) {
        int r = r0 + tid;
        toks[tid] = x[(r & 255) * TT + (r >> 8)];   // r = t*256+b
    }
    __syncthreads();
    for (int idx = tid; idx < 128 * 100; idx += 512) {
        int row = idx / 100, k = idx % 100;
        sh[row][k] = emb[(long)toks[row] * EE + k];
    }
    __syncthreads();
    for (int idx = tid; idx < 100 * 128; idx += 512) {
        int k = idx >> 7, j = idx & 127;
        float v = sh[j][k];
        d_xeT[(long)k * MROWS + r0 + j] = pack2(v, v);
    }
}

// ---------------- GEMM template: C[M,NPAD] = A_dup^T @ B (+bias) ----------------
// BM=128, BN=128, BK=20, 512 threads, TM=8, TN=4, f32x2, reg-prefetch dbl buffer.
template <int KT, bool BIAS>
__device__ __forceinline__ void gemm_body(const ULL* __restrict__ Adup,
                                          const float* __restrict__ Bw,
                                          const float* __restrict__ bias,
                                          float* __restrict__ Cout) {
    __shared__ __align__(16) ULL   As[20][128];
    __shared__ __align__(16) float Bs[20][128];
    const int tid = threadIdx.x;
    const int tx = tid & 31;
    const int ty = tid >> 5;
    const int r0 = blockIdx.x * 128;
    const int c0 = blockIdx.y * 128;

    ULL acc[8][2];
    if (BIAS) {
        ulonglong2 bp = *(const ulonglong2*)&bias[c0 + tx * 4];
#pragma unroll
        for (int i = 0; i < 8; i++) { acc[i][0] = bp.x; acc[i][1] = bp.y; }
    } else {
#pragma unroll
        for (int i = 0; i < 8; i++) { acc[i][0] = 0ull; acc[i][1] = 0ull; }
    }

    ULL apf[5]; float bpf[5];
#pragma unroll
    for (int j = 0; j < 5; j++) {
        int idx = tid + 512 * j;
        int kk = idx >> 7, rr = idx & 127;
        apf[j] = Adup[(long)kk * MROWS + r0 + rr];
        bpf[j] = Bw[kk * NPAD + c0 + rr];
    }

    for (int kt = 0; kt < KT; kt++) {
#pragma unroll
        for (int j = 0; j < 5; j++) {
            int idx = tid + 512 * j;
            int kk = idx >> 7, rr = idx & 127;
            As[kk][rr] = apf[j];
            Bs[kk][rr] = bpf[j];
        }
        __syncthreads();
        if (kt + 1 < KT) {
            int kbase = (kt + 1) * 20;
#pragma unroll
            for (int j = 0; j < 5; j++) {
                int idx = tid + 512 * j;
                int kk = idx >> 7, rr = idx & 127;
                apf[j] = Adup[(long)(kbase + kk) * MROWS + r0 + rr];
                bpf[j] = Bw[(kbase + kk) * NPAD + c0 + rr];
            }
        }
#pragma unroll
        for (int kk = 0; kk < 20; kk++) {
            ulonglong2 bp = *(const ulonglong2*)&Bs[kk][tx * 4];
#pragma unroll
            for (int i2 = 0; i2 < 4; i2++) {
                ulonglong2 a2 = *(const ulonglong2*)&As[kk][ty * 8 + i2 * 2];
                ffma2(acc[i2 * 2][0],     a2.x, bp.x);
                ffma2(acc[i2 * 2][1],     a2.x, bp.y);
                ffma2(acc[i2 * 2 + 1][0], a2.y, bp.x);
                ffma2(acc[i2 * 2 + 1][1], a2.y, bp.y);
            }
        }
        __syncthreads();
    }
#pragma unroll
    for (int i = 0; i < 8; i++) {
        float2 v0 = unpack2(acc[i][0]);
        float2 v1 = unpack2(acc[i][1]);
        *(float4*)&Cout[(long)(r0 + ty * 8 + i) * NPAD + c0 + tx * 4] =
            make_float4(v0.x, v0.y, v1.x, v1.y);
    }
}

__global__ __launch_bounds__(512) void gates_gemm_k() {
    gemm_body<5, true>(d_xeT, d_WtIn, d_bsum, d_gin);
}
__global__ __launch_bounds__(512) void s_gemm_k() {
    gemm_body<10, false>(d_h2T, d_WtS, nullptr, d_S);
}

// ---------------- LSTM recurrence: Whh in registers ------------------------------
// 128 blocks: dir = blk>>6, batch base = (blk&63)*4. Thread j<400 owns gate row j.
__global__ __launch_bounds__(416, 1) void lstm_k(const float* __restrict__ Whh_f,
                                                 const float* __restrict__ Whh_b) {
    __shared__ __align__(16) float hsh[4 * 100];   // [b][k]
    __shared__ float gsh[4 * 400];                 // [b][gate*100+hid]
    const int tid = threadIdx.x;
    const int dir = blockIdx.x >> 6;
    const int b0 = (blockIdx.x & 63) * 4;
    const float* __restrict__ Whh = dir ? Whh_b : Whh_f;

    ULL wreg[50];
    if (tid < 400) {
        const ULL* row = (const ULL*)(Whh + tid * 100);
#pragma unroll
        for (int kk = 0; kk < 50; kk++) wreg[kk] = row[kk];
    }
    for (int idx = tid; idx < 400; idx += 416) hsh[idx] = 0.0f;
    __syncthreads();

    float c = 0.0f;
    const int bb = tid / 100;
    const int hid = tid % 100;

    for (int step = 0; step < TT; ++step) {
        const int t = dir ? (TT - 1 - step) : step;
        if (tid < 400) {
            const float* gp = &d_gin[(long)(t * 256 + b0) * NPAD + dir * 400 + tid];
            float g0 = gp[0], g1 = gp[NPAD], g2 = gp[2 * NPAD], g3 = gp[3 * NPAD];
            ULL s0 = 0, s1 = 0, s2 = 0, s3 = 0;
#pragma unroll
            for (int kk = 0; kk < 25; ++kk) {
                ulonglong2 h0 = *(const ulonglong2*)&hsh[0 * 100 + kk * 4];
                ulonglong2 h1 = *(const ulonglong2*)&hsh[1 * 100 + kk * 4];
                ulonglong2 h2 = *(const ulonglong2*)&hsh[2 * 100 + kk * 4];
                ulonglong2 h3 = *(const ulonglong2*)&hsh[3 * 100 + kk * 4];
                ULL wa = wreg[2 * kk], wb = wreg[2 * kk + 1];
                ffma2(s0, wa, h0.x); ffma2(s0, wb, h0.y);
                ffma2(s1, wa, h1.x); ffma2(s1, wb, h1.y);
                ffma2(s2, wa, h2.x); ffma2(s2, wb, h2.y);
                ffma2(s3, wa, h3.x); ffma2(s3, wb, h3.y);
            }
            float2 f0 = unpack2(s0), f1 = unpack2(s1), f2 = unpack2(s2), f3 = unpack2(s3);
            gsh[0 * 400 + tid] = g0 + f0.x + f0.y;
            gsh[1 * 400 + tid] = g1 + f1.x + f1.y;
            gsh[2 * 400 + tid] = g2 + f2.x + f2.y;
            gsh[3 * 400 + tid] = g3 + f3.x + f3.y;
        }
        __syncthreads();
        if (tid < 400) {
            float gi = gsh[bb * 400 + hid];
            float gf = gsh[bb * 400 + hid + 100];
            float gg = gsh[bb * 400 + hid + 200];
            float go = gsh[bb * 400 + hid + 300];
            c = sigf(gf) * c + sigf(gi) * tanhf_fast(gg);
            float h = sigf(go) * tanhf_fast(c);
            hsh[bb * 100 + hid] = h;
            d_h2T[(long)(dir * 100 + hid) * MROWS + (b0 + bb) * TT + t] = pack2(h, h);
        }
        __syncthreads();
    }
}

// ---------------- combine: gather + tanh + (300->3) + softmax --------------------
__global__ __launch_bounds__(256) void combine_k(const int* __restrict__ paths,
                                                 const float* __restrict__ b1,
                                                 const float* __restrict__ W2,
                                                 const float* __restrict__ b2,
                                                 float* __restrict__ out) {
    const int warp = (blockIdx.x * blockDim.x + threadIdx.x) >> 5;
    const int lane = threadIdx.x & 31;
    if (warp >= BB * CC) return;
    const int b = warp / CC;

    const int* p = &paths[warp * 3];
    int p0 = __ldg(p), p1 = __ldg(p + 1), p2 = __ldg(p + 2);
    int i0 = min(max(p0, 0), TT - 1);
    int i1 = min(max(p1, 0), TT - 1);
    int i2 = min(max(p2, 0), TT - 1);

    const float* S0 = &d_S[(long)(b * TT + i0) * NPAD];
    const float* S1 = &d_S[(long)(b * TT + i1) * NPAD + 300];
    const float* S2 = &d_S[(long)(b * TT + i2) * NPAD + 600];

    float z0 = 0.f, z1 = 0.f, z2 = 0.f;
    for (int m = lane; m < MLPD; m += 32) {
        float hv = __ldg(&b1[m]);
        if (p0 >= 0) hv += S0[m];
        if (p1 >= 0) hv += S1[m];
        if (p2 >= 0) hv += S2[m];
        hv = tanhf_fast(hv);
        z0 = fmaf(hv, __ldg(&W2[m * 3 + 0]), z0);
        z1 = fmaf(hv, __ldg(&W2[m * 3 + 1]), z1);
        z2 = fmaf(hv, __ldg(&W2[m * 3 + 2]), z2);
    }
#pragma unroll
    for (int off = 16; off; off >>= 1) {
        z0 += __shfl_xor_sync(0xFFFFFFFFu, z0, off);
        z1 += __shfl_xor_sync(0xFFFFFFFFu, z1, off);
        z2 += __shfl_xor_sync(0xFFFFFFFFu, z2, off);
    }
    if (lane == 0) {
        z0 += __ldg(&b2[0]); z1 += __ldg(&b2[1]); z2 += __ldg(&b2[2]);
        float mx = fmaxf(z0, fmaxf(z1, z2));
        float e0 = __expf(z0 - mx), e1 = __expf(z1 - mx), e2 = __expf(z2 - mx);
        float inv = 1.0f / (e0 + e1 + e2);
        out[warp * 3 + 0] = e0 * inv;
        out[warp * 3 + 1] = e1 * inv;
        out[warp * 3 + 2] = e2 * inv;
    }
}

// -------------------------------- launch -----------------------------------------
extern "C" void kernel_launch(void* const* d_in, const int* in_sizes, int n_in,
                              void* d_out, int out_size) {
    const int*   x     = (const int*)  d_in[0];
    const int*   paths = (const int*)  d_in[1];
    const float* emb   = (const float*)d_in[2];
    const float* Whh_f = (const float*)d_in[4];
    const float* Whh_b = (const float*)d_in[8];
    const float* W1    = (const float*)d_in[11];
    const float* b1    = (const float*)d_in[12];
    const float* W2    = (const float*)d_in[13];
    const float* b2    = (const float*)d_in[14];
    float* out = (float*)d_out;

    prep_k<<<128, 256>>>((const float*)d_in[3], (const float*)d_in[7],
                         (const float*)d_in[5], (const float*)d_in[6],
                         (const float*)d_in[9], (const float*)d_in[10], W1);

    xet_k<<<256, 512>>>(x, emb);

    { dim3 g(256, 7); gates_gemm_k<<<g, 512>>>(); }   // cols 0..895 (800 used)

    lstm_k<<<128, 416>>>(Whh_f, Whh_b);

    { dim3 g(256, 8); s_gemm_k<<<g, 512>>>(); }       // cols 0..1023 (900 used)

    {
        int warps = BB * CC;
        int blocks = (warps * 32 + 255) / 256;
        combine_k<<<blocks, 256>>>(paths, b1, W2, b2, out);
    }
}